// round 6
// baseline (speedup 1.0000x reference)
#include <cuda_runtime.h>
#include <math.h>
#include <stdint.h>

#define DD 256
#define AA 64
#define NROWS 4096   // B*N
#define NCTA 148     // persistent CTAs for attn
#define NBUF 3       // pipeline depth

// ---------------- scratch (device globals; no allocation allowed) ----------
__device__ float g_W2[DD * DD];      // scale * Wq^T @ Wk
__device__ float g_b2[DD];           // scale * bq @ Wk
__device__ float g_u[DD];            // scale * Wq^T @ bk
__device__ float g_c;                // scale * bq . bk
__device__ float g_Qk[NROWS * DD];   // cc @ g_W2 + g_b2
__device__ float g_qb[NROWS];        // cc_row . g_u + g_c
__device__ float g_wsum[NROWS * DD]; // sum_a p[a] * anchor[a,:]
__device__ float g_S[NROWS];         // sum_a p[a]

// ---------------- f32x2 helpers ---------------------------------------------
__device__ __forceinline__ unsigned long long pack2(float x, float y) {
    unsigned long long r;
    asm("mov.b64 %0, {%1, %2};" : "=l"(r) : "f"(x), "f"(y));
    return r;
}
__device__ __forceinline__ void unpack2(unsigned long long v, float& x, float& y) {
    asm("mov.b64 {%0, %1}, %2;" : "=f"(x), "=f"(y) : "l"(v));
}
__device__ __forceinline__ void fma2(unsigned long long& d, unsigned long long a,
                                     unsigned long long b) {
    asm("fma.rn.f32x2 %0, %1, %2, %0;" : "+l"(d) : "l"(a), "l"(b));
}

// ---------------- kernel A: g_W2 = scale * Wq^T @ Wk ------------------------
__device__ __forceinline__ void mma_tile(const float (*As)[68], const float (*Bs)[68],
                                         int ty, int tx, float acc[4][4]) {
#pragma unroll
    for (int kk = 0; kk < 16; ++kk) {
        float4 av = *reinterpret_cast<const float4*>(&As[kk][ty * 4]);
        float4 bv = *reinterpret_cast<const float4*>(&Bs[kk][tx * 4]);
        float ar[4] = {av.x, av.y, av.z, av.w};
        float br[4] = {bv.x, bv.y, bv.z, bv.w};
#pragma unroll
        for (int i = 0; i < 4; ++i)
#pragma unroll
            for (int j = 0; j < 4; ++j)
                acc[i][j] = fmaf(ar[i], br[j], acc[i][j]);
    }
}

__global__ __launch_bounds__(256) void prep_w2(const float* __restrict__ Wq,
                                               const float* __restrict__ Wk) {
    __shared__ float As[16][68];
    __shared__ float Bs[16][68];
    const float scale = 0.0625f;  // 1/sqrt(256)
    int tx = threadIdx.x % 16, ty = threadIdx.x / 16;
    int d0 = blockIdx.x * 64, e0 = blockIdx.y * 64;
    float acc[4][4] = {};
    for (int k0 = 0; k0 < DD; k0 += 16) {
        float4 a = *reinterpret_cast<const float4*>(Wq + (k0 + ty) * DD + d0 + tx * 4);
        float4 b = *reinterpret_cast<const float4*>(Wk + (k0 + ty) * DD + e0 + tx * 4);
        *reinterpret_cast<float4*>(&As[ty][tx * 4]) = a;
        *reinterpret_cast<float4*>(&Bs[ty][tx * 4]) = b;
        __syncthreads();
        mma_tile(As, Bs, ty, tx, acc);
        __syncthreads();
    }
#pragma unroll
    for (int i = 0; i < 4; ++i)
#pragma unroll
        for (int j = 0; j < 4; ++j)
            g_W2[(d0 + ty * 4 + i) * DD + e0 + tx * 4 + j] = scale * acc[i][j];
}

// ---------------- kernel A2: bias vectors ----------------------------------
__global__ __launch_bounds__(256) void prep_vec(const float* __restrict__ Wq,
                                                const float* __restrict__ bq,
                                                const float* __restrict__ Wk,
                                                const float* __restrict__ bk) {
    const float scale = 0.0625f;
    int t = threadIdx.x;
    if (blockIdx.x == 0) {
        float s = 0.f;
        for (int k = 0; k < DD; ++k) s = fmaf(Wq[k * DD + t], bk[k], s);
        g_u[t] = scale * s;
        if (t == 0) {
            float c = 0.f;
            for (int k = 0; k < DD; ++k) c = fmaf(bq[k], bk[k], c);
            g_c = scale * c;
        }
    } else {
        float s = 0.f;
        for (int k = 0; k < DD; ++k) s = fmaf(bq[k], Wk[k * DD + t], s);
        g_b2[t] = scale * s;
    }
}

// ---------------- big GEMM: C[4096,256] = A @ B (+bias) with FFMA2 ----------
// BMODE 0: A = Ap (cc), B = g_W2 [K,N] row-major, C = g_Qk, bias = g_b2[n];
//          blockIdx.y==0 also computes g_qb[m] = cc_row . g_u + g_c
// BMODE 1: A = g_wsum, B = Bp (Wv [N,K] -> transposed), C = Cp (out),
//          bias = biasp[n] * g_S[m]
template <int BMODE>
__global__ __launch_bounds__(256) void gemm128(const float* __restrict__ Ap,
                                               const float* __restrict__ Bp,
                                               const float* __restrict__ biasp,
                                               float* __restrict__ Cp) {
    __shared__ float As[2][16][132];
    __shared__ float Bs[2][16][68];
    __shared__ float s_u[DD];

    const float* A = (BMODE == 0) ? Ap : g_wsum;
    const float* B = (BMODE == 0) ? g_W2 : Bp;
    const float* bias = (BMODE == 0) ? g_b2 : biasp;
    float* C = (BMODE == 0) ? g_Qk : Cp;

    const int t = threadIdx.x;
    const int tx = t & 15, ty = t >> 4;
    const int m0 = blockIdx.x * 128, n0 = blockIdx.y * 64;
    const int lmA = t >> 1, kA = (t & 1) * 8;   // A staging
    const int kB = t >> 4, nB = (t & 15) * 4;   // B staging (BMODE 0)
    const int nW = t >> 2, kW = (t & 3) * 4;    // B staging (BMODE 1)
    const bool qb_active = (BMODE == 0) && (blockIdx.y == 0);

    float4 a0, a1, b0;
    a0 = *reinterpret_cast<const float4*>(A + (m0 + lmA) * DD + kA);
    a1 = *reinterpret_cast<const float4*>(A + (m0 + lmA) * DD + kA + 4);
    if (BMODE == 0)
        b0 = *reinterpret_cast<const float4*>(B + kB * DD + n0 + nB);
    else
        b0 = *reinterpret_cast<const float4*>(B + (n0 + nW) * DD + kW);
    if (qb_active) s_u[t] = g_u[t];
    {
        float av[8] = {a0.x, a0.y, a0.z, a0.w, a1.x, a1.y, a1.z, a1.w};
#pragma unroll
        for (int c = 0; c < 8; ++c) As[0][kA + c][lmA] = av[c];
        if (BMODE == 0) {
            *reinterpret_cast<float4*>(&Bs[0][kB][nB]) = b0;
        } else {
            float bvv[4] = {b0.x, b0.y, b0.z, b0.w};
#pragma unroll
            for (int c = 0; c < 4; ++c) Bs[0][kW + c][nW] = bvv[c];
        }
    }
    __syncthreads();

    unsigned long long acc[4][4];
#pragma unroll
    for (int i = 0; i < 4; ++i)
#pragma unroll
        for (int j = 0; j < 4; ++j) acc[i][j] = pack2(0.f, 0.f);
    float qb_part = 0.f;

    for (int c = 0; c < 16; ++c) {
        const int buf = c & 1;
        if (c + 1 < 16) {
            const int k0 = (c + 1) * 16;
            a0 = *reinterpret_cast<const float4*>(A + (m0 + lmA) * DD + k0 + kA);
            a1 = *reinterpret_cast<const float4*>(A + (m0 + lmA) * DD + k0 + kA + 4);
            if (BMODE == 0)
                b0 = *reinterpret_cast<const float4*>(B + (k0 + kB) * DD + n0 + nB);
            else
                b0 = *reinterpret_cast<const float4*>(B + (n0 + nW) * DD + k0 + kW);
        }
#pragma unroll
        for (int kk = 0; kk < 16; ++kk) {
            const ulonglong2* ap =
                reinterpret_cast<const ulonglong2*>(&As[buf][kk][ty * 8]);
            ulonglong2 A01 = ap[0], A23 = ap[1];
            float4 bf = *reinterpret_cast<const float4*>(&Bs[buf][kk][tx * 4]);
            unsigned long long bd0 = pack2(bf.x, bf.x), bd1 = pack2(bf.y, bf.y);
            unsigned long long bd2 = pack2(bf.z, bf.z), bd3 = pack2(bf.w, bf.w);
            unsigned long long a2[4] = {A01.x, A01.y, A23.x, A23.y};
#pragma unroll
            for (int i = 0; i < 4; ++i) {
                fma2(acc[i][0], a2[i], bd0);
                fma2(acc[i][1], a2[i], bd1);
                fma2(acc[i][2], a2[i], bd2);
                fma2(acc[i][3], a2[i], bd3);
            }
        }
        if (qb_active) {
#pragma unroll
            for (int j = 0; j < 8; ++j)
                qb_part = fmaf(As[buf][kA + j][lmA], s_u[c * 16 + kA + j], qb_part);
        }
        if (c + 1 < 16) {
            float av[8] = {a0.x, a0.y, a0.z, a0.w, a1.x, a1.y, a1.z, a1.w};
#pragma unroll
            for (int c2 = 0; c2 < 8; ++c2) As[buf ^ 1][kA + c2][lmA] = av[c2];
            if (BMODE == 0) {
                *reinterpret_cast<float4*>(&Bs[buf ^ 1][kB][nB]) = b0;
            } else {
                float bvv[4] = {b0.x, b0.y, b0.z, b0.w};
#pragma unroll
                for (int c2 = 0; c2 < 4; ++c2) Bs[buf ^ 1][kW + c2][nW] = bvv[c2];
            }
        }
        __syncthreads();
    }

    if (qb_active) {
        float p = qb_part + __shfl_down_sync(0xffffffffu, qb_part, 1);
        if ((t & 1) == 0) g_qb[m0 + lmA] = p + g_c;
    }

    float4 bb = *reinterpret_cast<const float4*>(bias + n0 + tx * 4);
#pragma unroll
    for (int i = 0; i < 4; ++i) {
        const int m = m0 + ty * 8 + 2 * i;
        float lo[4], hi[4];
#pragma unroll
        for (int j = 0; j < 4; ++j) unpack2(acc[i][j], lo[j], hi[j]);
        float4 o0, o1;
        if (BMODE == 1) {
            float s0 = g_S[m], s1 = g_S[m + 1];
            o0 = make_float4(lo[0] + bb.x * s0, lo[1] + bb.y * s0,
                             lo[2] + bb.z * s0, lo[3] + bb.w * s0);
            o1 = make_float4(hi[0] + bb.x * s1, hi[1] + bb.y * s1,
                             hi[2] + bb.z * s1, hi[3] + bb.w * s1);
        } else {
            o0 = make_float4(lo[0] + bb.x, lo[1] + bb.y, lo[2] + bb.z, lo[3] + bb.w);
            o1 = make_float4(hi[0] + bb.x, hi[1] + bb.y, hi[2] + bb.z, hi[3] + bb.w);
        }
        *reinterpret_cast<float4*>(C + (size_t)m * DD + n0 + tx * 4) = o0;
        *reinterpret_cast<float4*>(C + (size_t)(m + 1) * DD + n0 + tx * 4) = o1;
    }
}

// ---------------- attn v4: 512 thr, depth-3 bulk-async, reg prefetch --------
__global__ __launch_bounds__(512) void attn_v4(const float* __restrict__ anchor,
                                               const float* __restrict__ sims) {
    extern __shared__ float sm[];
    float* sQk    = sm + NBUF * AA * DD;   // [2][256]
    float* s_sims = sQk + 2 * DD;          // [2][64]
    float* s_wpart = s_sims + 2 * AA;      // [256]
    __shared__ float s_adj[AA], s_p[AA];
    __shared__ __align__(8) unsigned long long mbar[NBUF];

    const int t = threadIdx.x, w = t >> 5, lane = t & 31;
    const int cta = blockIdx.x;
    const int iters = (NROWS - cta + NCTA - 1) / NCTA;

    uint32_t mb_base, sA_base;
    asm("{ .reg .u64 x; cvta.to.shared.u64 x, %1; cvt.u32.u64 %0, x; }"
        : "=r"(mb_base) : "l"(mbar));
    asm("{ .reg .u64 x; cvta.to.shared.u64 x, %1; cvt.u32.u64 %0, x; }"
        : "=r"(sA_base) : "l"(sm));

    if (t == 0) {
#pragma unroll
        for (int j = 0; j < NBUF; ++j)
            asm volatile("mbarrier.init.shared::cta.b64 [%0], 1;"
                         :: "r"(mb_base + j * 8));
    }
    __syncthreads();
    if (t == 0) {
#pragma unroll
        for (int j = 0; j < NBUF; ++j)
            if (j < iters) {
                uint32_t mb = mb_base + j * 8;
                asm volatile("mbarrier.arrive.expect_tx.shared::cta.b64 _, [%0], %1;"
                             :: "r"(mb), "r"(65536));
                asm volatile(
                    "cp.async.bulk.shared::cta.global.mbarrier::complete_tx::bytes "
                    "[%0], [%1], %2, [%3];"
                    :: "r"(sA_base + j * 65536),
                       "l"(anchor + (size_t)(cta + j * NCTA) * AA * DD),
                       "r"(65536), "r"(mb) : "memory");
            }
    }
    // preload row0 vectors
    if (t < DD) sQk[t] = g_Qk[cta * DD + t];
    if (t < AA) s_sims[t] = sims[cta * AA + t];
    float qb_cur = g_qb[cta];
    int phase[NBUF];
#pragma unroll
    for (int j = 0; j < NBUF; ++j) phase[j] = 0;
    __syncthreads();

    for (int it = 0; it < iters; ++it) {
        const int row = cta + it * NCTA;
        const int b = it % NBUF;
        const int cb = it & 1;
        const float* sA = sm + b * AA * DD;

        // prefetch next row vectors into regs
        const bool has_next = (it + 1 < iters);
        float r_qk = 0.f, r_sims = 0.f, r_qb = 0.f;
        if (has_next) {
            const int nrow = row + NCTA;
            if (t < DD) r_qk = g_Qk[nrow * DD + t];
            if (t < AA) r_sims = sims[nrow * AA + t];
            r_qb = g_qb[nrow];
        }

        // wait for this buffer's tile
        {
            uint32_t mb = mb_base + b * 8;
            asm volatile(
                "{ .reg .pred P;\n"
                "WL%=: mbarrier.try_wait.parity.acquire.cta.shared::cta.b64 P, [%0], %1;\n"
                "@!P bra WL%=; }"
                :: "r"(mb), "r"(phase[b]) : "memory");
            phase[b] ^= 1;
        }

        // scores: anchor a = t>>3, 8 lanes per anchor, 32 dims each
        {
            const int a = t >> 3, sub = t & 7;
            const float4* a4 = reinterpret_cast<const float4*>(sA + a * DD) + sub * 8;
            const float4* q4 = reinterpret_cast<const float4*>(sQk + cb * DD) + sub * 8;
            float s = 0.f;
#pragma unroll
            for (int j = 0; j < 8; ++j) {
                float4 qv = q4[j], xv = a4[j];
                s = fmaf(qv.x, xv.x, s);
                s = fmaf(qv.y, xv.y, s);
                s = fmaf(qv.z, xv.z, s);
                s = fmaf(qv.w, xv.w, s);
            }
            s += __shfl_down_sync(0xffffffffu, s, 4);
            s += __shfl_down_sync(0xffffffffu, s, 2);
            s += __shfl_down_sync(0xffffffffu, s, 1);
            if (sub == 0) s_adj[a] = s + qb_cur + s_sims[cb * AA + a];
        }
        __syncthreads();

        // conditional softmax (warp 0 owns all 64 logits)
        if (w == 0) {
            float v0 = s_adj[lane], v1 = s_adj[lane + 32];
            float sum = v0 + v1;
#pragma unroll
            for (int o = 16; o; o >>= 1) sum += __shfl_xor_sync(0xffffffffu, sum, o);
            if (sum != 0.0f) {
                float m = fmaxf(v0, v1);
#pragma unroll
                for (int o = 16; o; o >>= 1)
                    m = fmaxf(m, __shfl_xor_sync(0xffffffffu, m, o));
                float e0 = __expf(v0 - m), e1 = __expf(v1 - m);
                float es = e0 + e1;
#pragma unroll
                for (int o = 16; o; o >>= 1) es += __shfl_xor_sync(0xffffffffu, es, o);
                float p0 = e0 / es, p1 = e1 / es;
                s_p[lane] = p0;
                s_p[lane + 32] = p1;
                float ps = p0 + p1;
#pragma unroll
                for (int o = 16; o; o >>= 1) ps += __shfl_xor_sync(0xffffffffu, ps, o);
                if (lane == 0) g_S[row] = ps;
            } else {
                s_p[lane] = v0;
                s_p[lane + 32] = v1;
                if (lane == 0) g_S[row] = sum;  // == 0
            }
        }
        __syncthreads();

        // weighted sum split over 2 thread-halves
        {
            const int h = t >> 8, d = t & 255;
            const float* base = sA + h * 32 * DD + d;
            float acc = 0.f;
#pragma unroll
            for (int a2 = 0; a2 < 32; ++a2)
                acc = fmaf(s_p[h * 32 + a2], base[a2 * DD], acc);
            if (h == 1) s_wpart[d] = acc;
            __syncthreads();
            if (h == 0) g_wsum[row * DD + d] = acc + s_wpart[d];
        }

        // refill this buffer (all sA reads completed before last barrier)
        if (t == 0 && it + NBUF < iters) {
            uint32_t mb = mb_base + b * 8;
            asm volatile("mbarrier.arrive.expect_tx.shared::cta.b64 _, [%0], %1;"
                         :: "r"(mb), "r"(65536));
            asm volatile(
                "cp.async.bulk.shared::cta.global.mbarrier::complete_tx::bytes "
                "[%0], [%1], %2, [%3];"
                :: "r"(sA_base + b * 65536),
                   "l"(anchor + (size_t)(row + NBUF * NCTA) * AA * DD),
                   "r"(65536), "r"(mb) : "memory");
        }

        // park prefetched vectors for next iter
        if (has_next) {
            if (t < DD) sQk[(cb ^ 1) * DD + t] = r_qk;
            if (t < AA) s_sims[(cb ^ 1) * AA + t] = r_sims;
            qb_cur = r_qb;
        }
        __syncthreads();
    }
}

// ---------------- launch ----------------------------------------------------
extern "C" void kernel_launch(void* const* d_in, const int* in_sizes, int n_in,
                              void* d_out, int out_size) {
    const float* cc     = (const float*)d_in[0];
    const float* anchor = (const float*)d_in[1];
    const float* sims   = (const float*)d_in[2];
    const float* Wq     = (const float*)d_in[3];
    const float* bq     = (const float*)d_in[4];
    const float* Wk     = (const float*)d_in[5];
    const float* bk     = (const float*)d_in[6];
    const float* Wv     = (const float*)d_in[7];
    const float* bv     = (const float*)d_in[8];
    float* out = (float*)d_out;

    const int smem_attn =
        (NBUF * AA * DD + 2 * DD + 2 * AA + DD) * (int)sizeof(float);  // ~200 KB
    cudaFuncSetAttribute(attn_v4, cudaFuncAttributeMaxDynamicSharedMemorySize,
                         smem_attn);

    prep_w2<<<dim3(4, 4), 256>>>(Wq, Wk);
    prep_vec<<<2, 256>>>(Wq, bq, Wk, bk);
    gemm128<0><<<dim3(32, 4), 256>>>(cc, nullptr, nullptr, nullptr);
    attn_v4<<<NCTA, 512, smem_attn>>>(anchor, sims);
    gemm128<1><<<dim3(32, 4), 256>>>(nullptr, Wv, bv, out);
}

// round 7
// speedup vs baseline: 1.6583x; 1.6583x over previous
#include <cuda_runtime.h>
#include <math.h>
#include <stdint.h>

#define DD 256
#define AA 64
#define NROWS 4096   // B*N
#define NCTA 148     // persistent CTAs for attn
#define NBUF 3       // pipeline depth

// ---------------- scratch (device globals; no allocation allowed) ----------
__device__ float g_W2[DD * DD];      // scale * Wq^T @ Wk
__device__ float g_b2[DD];           // scale * bq @ Wk
__device__ float g_u[DD];            // scale * Wq^T @ bk
__device__ float g_c;                // scale * bq . bk
__device__ float g_Qk[NROWS * DD];   // cc @ g_W2 + g_b2
__device__ float g_qb[NROWS];        // cc_row . g_u + g_c
__device__ float g_wsum[NROWS * DD]; // sum_a p[a] * anchor[a,:]
__device__ float g_S[NROWS];         // sum_a p[a]

// ---------------- f32x2 helpers ---------------------------------------------
__device__ __forceinline__ unsigned long long pack2(float x, float y) {
    unsigned long long r;
    asm("mov.b64 %0, {%1, %2};" : "=l"(r) : "f"(x), "f"(y));
    return r;
}
__device__ __forceinline__ void unpack2(unsigned long long v, float& x, float& y) {
    asm("mov.b64 {%0, %1}, %2;" : "=f"(x), "=f"(y) : "l"(v));
}
__device__ __forceinline__ void fma2(unsigned long long& d, unsigned long long a,
                                     unsigned long long b) {
    asm("fma.rn.f32x2 %0, %1, %2, %0;" : "+l"(d) : "l"(a), "l"(b));
}

// ---------------- kernel A: g_W2 = scale * Wq^T @ Wk ------------------------
__device__ __forceinline__ void mma_tile4(const float (*As)[68], const float (*Bs)[68],
                                          int ty, int tx, float acc[4][4]) {
#pragma unroll
    for (int kk = 0; kk < 16; ++kk) {
        float4 av = *reinterpret_cast<const float4*>(&As[kk][ty * 4]);
        float4 bv = *reinterpret_cast<const float4*>(&Bs[kk][tx * 4]);
        float ar[4] = {av.x, av.y, av.z, av.w};
        float br[4] = {bv.x, bv.y, bv.z, bv.w};
#pragma unroll
        for (int i = 0; i < 4; ++i)
#pragma unroll
            for (int j = 0; j < 4; ++j)
                acc[i][j] = fmaf(ar[i], br[j], acc[i][j]);
    }
}

__global__ __launch_bounds__(256) void prep_w2(const float* __restrict__ Wq,
                                               const float* __restrict__ Wk) {
    __shared__ float As[16][68];
    __shared__ float Bs[16][68];
    const float scale = 0.0625f;  // 1/sqrt(256)
    int tx = threadIdx.x % 16, ty = threadIdx.x / 16;
    int d0 = blockIdx.x * 64, e0 = blockIdx.y * 64;
    float acc[4][4] = {};
    for (int k0 = 0; k0 < DD; k0 += 16) {
        float4 a = *reinterpret_cast<const float4*>(Wq + (k0 + ty) * DD + d0 + tx * 4);
        float4 b = *reinterpret_cast<const float4*>(Wk + (k0 + ty) * DD + e0 + tx * 4);
        *reinterpret_cast<float4*>(&As[ty][tx * 4]) = a;
        *reinterpret_cast<float4*>(&Bs[ty][tx * 4]) = b;
        __syncthreads();
        mma_tile4(As, Bs, ty, tx, acc);
        __syncthreads();
    }
#pragma unroll
    for (int i = 0; i < 4; ++i)
#pragma unroll
        for (int j = 0; j < 4; ++j)
            g_W2[(d0 + ty * 4 + i) * DD + e0 + tx * 4 + j] = scale * acc[i][j];
}

// ---------------- kernel A2: bias vectors ----------------------------------
__global__ __launch_bounds__(256) void prep_vec(const float* __restrict__ Wq,
                                                const float* __restrict__ bq,
                                                const float* __restrict__ Wk,
                                                const float* __restrict__ bk) {
    const float scale = 0.0625f;
    int t = threadIdx.x;
    if (blockIdx.x == 0) {
        float s = 0.f;
        for (int k = 0; k < DD; ++k) s = fmaf(Wq[k * DD + t], bk[k], s);
        g_u[t] = scale * s;
        if (t == 0) {
            float c = 0.f;
            for (int k = 0; k < DD; ++k) c = fmaf(bq[k], bk[k], c);
            g_c = scale * c;
        }
    } else {
        float s = 0.f;
        for (int k = 0; k < DD; ++k) s = fmaf(bq[k], Wk[k * DD + t], s);
        g_b2[t] = scale * s;
    }
}

// ---------------- big GEMM: C[4096,256] = A @ B (+bias), 64x64 tile, FFMA2 --
// BMODE 0: A = Ap (cc), B = g_W2 [K,N] row-major, C = g_Qk, bias = g_b2[n];
//          blockIdx.y==0 also computes g_qb[m] = cc_row . g_u + g_c
// BMODE 1: A = g_wsum, B = Bp (Wv [N,K] -> transposed), C = Cp (out),
//          bias = biasp[n] * g_S[m]
template <int BMODE>
__global__ __launch_bounds__(256) void gemm64(const float* __restrict__ Ap,
                                              const float* __restrict__ Bp,
                                              const float* __restrict__ biasp,
                                              float* __restrict__ Cp) {
    __shared__ float As[2][16][68];
    __shared__ float Bs[2][16][68];
    __shared__ float s_u[DD];

    const float* A = (BMODE == 0) ? Ap : g_wsum;
    const float* B = (BMODE == 0) ? g_W2 : Bp;
    const float* bias = (BMODE == 0) ? g_b2 : biasp;
    float* C = (BMODE == 0) ? g_Qk : Cp;

    const int t = threadIdx.x;
    const int tx = t & 15, ty = t >> 4;
    const int m0 = blockIdx.x * 64, n0 = blockIdx.y * 64;
    const int lmA = t >> 2, kA = (t & 3) * 4;   // A staging (64 rows x 16 k)
    const int kB = t >> 4, nB = (t & 15) * 4;   // B staging (BMODE 0)
    const int nW = t >> 2, kW = (t & 3) * 4;    // B staging (BMODE 1)
    const bool qb_active = (BMODE == 0) && (blockIdx.y == 0);

    if (qb_active) s_u[t] = g_u[t];

    float4 a0, b0;
    a0 = *reinterpret_cast<const float4*>(A + (m0 + lmA) * DD + kA);
    if (BMODE == 0)
        b0 = *reinterpret_cast<const float4*>(B + kB * DD + n0 + nB);
    else
        b0 = *reinterpret_cast<const float4*>(B + (n0 + nW) * DD + kW);
    {
        float av[4] = {a0.x, a0.y, a0.z, a0.w};
#pragma unroll
        for (int c = 0; c < 4; ++c) As[0][kA + c][lmA] = av[c];
        if (BMODE == 0) {
            *reinterpret_cast<float4*>(&Bs[0][kB][nB]) = b0;
        } else {
            float bvv[4] = {b0.x, b0.y, b0.z, b0.w};
#pragma unroll
            for (int c = 0; c < 4; ++c) Bs[0][kW + c][nW] = bvv[c];
        }
    }
    __syncthreads();

    unsigned long long acc[2][4];
#pragma unroll
    for (int i = 0; i < 2; ++i)
#pragma unroll
        for (int j = 0; j < 4; ++j) acc[i][j] = pack2(0.f, 0.f);
    float qb_part = 0.f;

    for (int c = 0; c < 16; ++c) {
        const int buf = c & 1;
        if (c + 1 < 16) {
            const int k0 = (c + 1) * 16;
            a0 = *reinterpret_cast<const float4*>(A + (m0 + lmA) * DD + k0 + kA);
            if (BMODE == 0)
                b0 = *reinterpret_cast<const float4*>(B + (k0 + kB) * DD + n0 + nB);
            else
                b0 = *reinterpret_cast<const float4*>(B + (n0 + nW) * DD + k0 + kW);
        }
#pragma unroll
        for (int kk = 0; kk < 16; ++kk) {
            ulonglong2 ap = *reinterpret_cast<const ulonglong2*>(&As[buf][kk][ty * 4]);
            float4 bf = *reinterpret_cast<const float4*>(&Bs[buf][kk][tx * 4]);
            unsigned long long bd0 = pack2(bf.x, bf.x), bd1 = pack2(bf.y, bf.y);
            unsigned long long bd2 = pack2(bf.z, bf.z), bd3 = pack2(bf.w, bf.w);
            unsigned long long a2[2] = {ap.x, ap.y};
#pragma unroll
            for (int i = 0; i < 2; ++i) {
                fma2(acc[i][0], a2[i], bd0);
                fma2(acc[i][1], a2[i], bd1);
                fma2(acc[i][2], a2[i], bd2);
                fma2(acc[i][3], a2[i], bd3);
            }
        }
        if (qb_active) {
#pragma unroll
            for (int j = 0; j < 4; ++j)
                qb_part = fmaf(As[buf][kA + j][lmA], s_u[c * 16 + kA + j], qb_part);
        }
        if (c + 1 < 16) {
            float av[4] = {a0.x, a0.y, a0.z, a0.w};
#pragma unroll
            for (int c2 = 0; c2 < 4; ++c2) As[buf ^ 1][kA + c2][lmA] = av[c2];
            if (BMODE == 0) {
                *reinterpret_cast<float4*>(&Bs[buf ^ 1][kB][nB]) = b0;
            } else {
                float bvv[4] = {b0.x, b0.y, b0.z, b0.w};
#pragma unroll
                for (int c2 = 0; c2 < 4; ++c2) Bs[buf ^ 1][kW + c2][nW] = bvv[c2];
            }
        }
        __syncthreads();
    }

    if (qb_active) {
        // 4 consecutive lanes (t&3) share one m-row
        float p = qb_part + __shfl_down_sync(0xffffffffu, qb_part, 2);
        p += __shfl_down_sync(0xffffffffu, p, 1);
        if ((t & 3) == 0) g_qb[m0 + lmA] = p + g_c;
    }

    float4 bb = *reinterpret_cast<const float4*>(bias + n0 + tx * 4);
#pragma unroll
    for (int i = 0; i < 2; ++i) {
        const int m = m0 + ty * 4 + 2 * i;
        float lo[4], hi[4];
#pragma unroll
        for (int j = 0; j < 4; ++j) unpack2(acc[i][j], lo[j], hi[j]);
        float4 o0, o1;
        if (BMODE == 1) {
            float s0 = g_S[m], s1 = g_S[m + 1];
            o0 = make_float4(lo[0] + bb.x * s0, lo[1] + bb.y * s0,
                             lo[2] + bb.z * s0, lo[3] + bb.w * s0);
            o1 = make_float4(hi[0] + bb.x * s1, hi[1] + bb.y * s1,
                             hi[2] + bb.z * s1, hi[3] + bb.w * s1);
        } else {
            o0 = make_float4(lo[0] + bb.x, lo[1] + bb.y, lo[2] + bb.z, lo[3] + bb.w);
            o1 = make_float4(hi[0] + bb.x, hi[1] + bb.y, hi[2] + bb.z, hi[3] + bb.w);
        }
        *reinterpret_cast<float4*>(C + (size_t)m * DD + n0 + tx * 4) = o0;
        *reinterpret_cast<float4*>(C + (size_t)(m + 1) * DD + n0 + tx * 4) = o1;
    }
}

// ---------------- attn v5: v4 pipeline + conflict-free score mapping --------
__global__ __launch_bounds__(512) void attn_v5(const float* __restrict__ anchor,
                                               const float* __restrict__ sims) {
    extern __shared__ float sm[];
    float* sQk     = sm + NBUF * AA * DD;  // [2][256]
    float* s_sims  = sQk + 2 * DD;         // [2][64]
    float* s_wpart = s_sims + 2 * AA;      // [256]
    __shared__ float s_adj[AA], s_p[AA];
    __shared__ __align__(8) unsigned long long mbar[NBUF];

    const int t = threadIdx.x, w = t >> 5, lane = t & 31;
    const int cta = blockIdx.x;
    const int iters = (NROWS - cta + NCTA - 1) / NCTA;

    uint32_t mb_base, sA_base;
    asm("{ .reg .u64 x; cvta.to.shared.u64 x, %1; cvt.u32.u64 %0, x; }"
        : "=r"(mb_base) : "l"(mbar));
    asm("{ .reg .u64 x; cvta.to.shared.u64 x, %1; cvt.u32.u64 %0, x; }"
        : "=r"(sA_base) : "l"(sm));

    if (t == 0) {
#pragma unroll
        for (int j = 0; j < NBUF; ++j)
            asm volatile("mbarrier.init.shared::cta.b64 [%0], 1;"
                         :: "r"(mb_base + j * 8));
    }
    __syncthreads();
    if (t == 0) {
#pragma unroll
        for (int j = 0; j < NBUF; ++j)
            if (j < iters) {
                uint32_t mb = mb_base + j * 8;
                asm volatile("mbarrier.arrive.expect_tx.shared::cta.b64 _, [%0], %1;"
                             :: "r"(mb), "r"(65536));
                asm volatile(
                    "cp.async.bulk.shared::cta.global.mbarrier::complete_tx::bytes "
                    "[%0], [%1], %2, [%3];"
                    :: "r"(sA_base + j * 65536),
                       "l"(anchor + (size_t)(cta + j * NCTA) * AA * DD),
                       "r"(65536), "r"(mb) : "memory");
            }
    }
    // preload row0 vectors
    if (t < DD) sQk[t] = g_Qk[cta * DD + t];
    if (t < AA) s_sims[t] = sims[cta * AA + t];
    float qb_cur = g_qb[cta];
    int phase[NBUF];
#pragma unroll
    for (int j = 0; j < NBUF; ++j) phase[j] = 0;
    __syncthreads();

    for (int it = 0; it < iters; ++it) {
        const int row = cta + it * NCTA;
        const int b = it % NBUF;
        const int cb = it & 1;
        const float* sA = sm + b * AA * DD;

        // prefetch next row vectors into regs (overlaps DMA wait)
        const bool has_next = (it + 1 < iters);
        float r_qk = 0.f, r_sims = 0.f, r_qb = 0.f;
        if (has_next) {
            const int nrow = row + NCTA;
            if (t < DD) r_qk = g_Qk[nrow * DD + t];
            if (t < AA) r_sims = sims[nrow * AA + t];
            r_qb = g_qb[nrow];
        }

        // hoist Qk for this row: lane-contiguous float4 (conflict-free)
        const float4* q4 = reinterpret_cast<const float4*>(sQk + cb * DD);
        float4 q0 = q4[lane], q1 = q4[lane + 32];

        // wait for this buffer's tile
        {
            uint32_t mb = mb_base + b * 8;
            asm volatile(
                "{ .reg .pred P;\n"
                "WL%=: mbarrier.try_wait.parity.acquire.cta.shared::cta.b64 P, [%0], %1;\n"
                "@!P bra WL%=; }"
                :: "r"(mb), "r"(phase[b]) : "memory");
            phase[b] ^= 1;
        }

        // scores: warp per anchor, 4 rounds (a = w + 16*r); lane float4 reads
#pragma unroll
        for (int r = 0; r < 4; ++r) {
            const int a = w + r * 16;
            const float4* a4 = reinterpret_cast<const float4*>(sA + a * DD);
            float4 x0 = a4[lane], x1 = a4[lane + 32];
            float s = q0.x * x0.x + q0.y * x0.y + q0.z * x0.z + q0.w * x0.w +
                      q1.x * x1.x + q1.y * x1.y + q1.z * x1.z + q1.w * x1.w;
#pragma unroll
            for (int o = 16; o; o >>= 1) s += __shfl_down_sync(0xffffffffu, s, o);
            if (lane == 0) s_adj[a] = s + qb_cur + s_sims[cb * AA + a];
        }
        __syncthreads();

        // conditional softmax (warp 0 owns all 64 logits)
        if (w == 0) {
            float v0 = s_adj[lane], v1 = s_adj[lane + 32];
            float sum = v0 + v1;
#pragma unroll
            for (int o = 16; o; o >>= 1) sum += __shfl_xor_sync(0xffffffffu, sum, o);
            if (sum != 0.0f) {
                float m = fmaxf(v0, v1);
#pragma unroll
                for (int o = 16; o; o >>= 1)
                    m = fmaxf(m, __shfl_xor_sync(0xffffffffu, m, o));
                float e0 = __expf(v0 - m), e1 = __expf(v1 - m);
                float es = e0 + e1;
#pragma unroll
                for (int o = 16; o; o >>= 1) es += __shfl_xor_sync(0xffffffffu, es, o);
                float inv = 1.0f / es;
                s_p[lane] = e0 * inv;
                s_p[lane + 32] = e1 * inv;
                if (lane == 0) g_S[row] = 1.0f;  // sum of softmax probs
            } else {
                s_p[lane] = v0;
                s_p[lane + 32] = v1;
                if (lane == 0) g_S[row] = 0.0f;  // raw sum == 0
            }
        }
        __syncthreads();

        // weighted sum split over 2 thread-halves (scalar, conflict-free)
        {
            const int h = t >> 8, d = t & 255;
            const float* base = sA + h * 32 * DD + d;
            float acc = 0.f;
#pragma unroll
            for (int a2 = 0; a2 < 32; ++a2)
                acc = fmaf(s_p[h * 32 + a2], base[a2 * DD], acc);
            if (h == 1) s_wpart[d] = acc;
            __syncthreads();
            if (h == 0) g_wsum[row * DD + d] = acc + s_wpart[d];
        }

        // refill this buffer (all sA reads done before the barrier above)
        if (t == 0 && it + NBUF < iters) {
            uint32_t mb = mb_base + b * 8;
            asm volatile("mbarrier.arrive.expect_tx.shared::cta.b64 _, [%0], %1;"
                         :: "r"(mb), "r"(65536));
            asm volatile(
                "cp.async.bulk.shared::cta.global.mbarrier::complete_tx::bytes "
                "[%0], [%1], %2, [%3];"
                :: "r"(sA_base + b * 65536),
                   "l"(anchor + (size_t)(row + NBUF * NCTA) * AA * DD),
                   "r"(65536), "r"(mb) : "memory");
        }

        // park prefetched vectors for next iter
        if (has_next) {
            if (t < DD) sQk[(cb ^ 1) * DD + t] = r_qk;
            if (t < AA) s_sims[(cb ^ 1) * AA + t] = r_sims;
            qb_cur = r_qb;
        }
        __syncthreads();
    }
}

// ---------------- launch ----------------------------------------------------
extern "C" void kernel_launch(void* const* d_in, const int* in_sizes, int n_in,
                              void* d_out, int out_size) {
    const float* cc     = (const float*)d_in[0];
    const float* anchor = (const float*)d_in[1];
    const float* sims   = (const float*)d_in[2];
    const float* Wq     = (const float*)d_in[3];
    const float* bq     = (const float*)d_in[4];
    const float* Wk     = (const float*)d_in[5];
    const float* bk     = (const float*)d_in[6];
    const float* Wv     = (const float*)d_in[7];
    const float* bv     = (const float*)d_in[8];
    float* out = (float*)d_out;

    const int smem_attn =
        (NBUF * AA * DD + 2 * DD + 2 * AA + DD) * (int)sizeof(float);  // ~196 KB
    cudaFuncSetAttribute(attn_v5, cudaFuncAttributeMaxDynamicSharedMemorySize,
                         smem_attn);

    prep_w2<<<dim3(4, 4), 256>>>(Wq, Wk);
    prep_vec<<<2, 256>>>(Wq, bq, Wk, bk);
    gemm64<0><<<dim3(64, 4), 256>>>(cc, nullptr, nullptr, nullptr);
    attn_v5<<<NCTA, 512, smem_attn>>>(anchor, sims);
    gemm64<1><<<dim3(64, 4), 256>>>(nullptr, Wv, bv, out);
}

// round 8
// speedup vs baseline: 1.7361x; 1.0469x over previous
#include <cuda_runtime.h>
#include <math.h>
#include <stdint.h>

#define DD 256
#define AA 64
#define NROWS 4096   // B*N
#define NCTA 148     // persistent CTAs for attn
#define NBUF 3       // pipeline depth

// ---------------- scratch (device globals; no allocation allowed) ----------
__device__ float g_W2[DD * DD];      // scale * Wq^T @ Wk
__device__ float g_b2[DD];           // scale * bq @ Wk
__device__ float g_u[DD];            // scale * Wq^T @ bk
__device__ float g_c;                // scale * bq . bk
__device__ float g_Qk[NROWS * DD];   // cc @ g_W2 + g_b2
__device__ float g_qb[NROWS];        // cc_row . g_u + g_c
__device__ float g_wsum[NROWS * DD]; // sum_a p[a] * anchor[a,:]
__device__ float g_S[NROWS];         // sum_a p[a]

// ---------------- f32x2 helpers ---------------------------------------------
__device__ __forceinline__ unsigned long long pack2(float x, float y) {
    unsigned long long r;
    asm("mov.b64 %0, {%1, %2};" : "=l"(r) : "f"(x), "f"(y));
    return r;
}
__device__ __forceinline__ void unpack2(unsigned long long v, float& x, float& y) {
    asm("mov.b64 {%0, %1}, %2;" : "=f"(x), "=f"(y) : "l"(v));
}
__device__ __forceinline__ void fma2(unsigned long long& d, unsigned long long a,
                                     unsigned long long b) {
    asm("fma.rn.f32x2 %0, %1, %2, %0;" : "+l"(d) : "l"(a), "l"(b));
}

// ---------------- kernel A: g_W2 = scale * Wq^T @ Wk ------------------------
__device__ __forceinline__ void mma_tile4(const float (*As)[68], const float (*Bs)[68],
                                          int ty, int tx, float acc[4][4]) {
#pragma unroll
    for (int kk = 0; kk < 16; ++kk) {
        float4 av = *reinterpret_cast<const float4*>(&As[kk][ty * 4]);
        float4 bv = *reinterpret_cast<const float4*>(&Bs[kk][tx * 4]);
        float ar[4] = {av.x, av.y, av.z, av.w};
        float br[4] = {bv.x, bv.y, bv.z, bv.w};
#pragma unroll
        for (int i = 0; i < 4; ++i)
#pragma unroll
            for (int j = 0; j < 4; ++j)
                acc[i][j] = fmaf(ar[i], br[j], acc[i][j]);
    }
}

__global__ __launch_bounds__(256) void prep_w2(const float* __restrict__ Wq,
                                               const float* __restrict__ Wk) {
    __shared__ float As[16][68];
    __shared__ float Bs[16][68];
    const float scale = 0.0625f;  // 1/sqrt(256)
    int tx = threadIdx.x % 16, ty = threadIdx.x / 16;
    int d0 = blockIdx.x * 64, e0 = blockIdx.y * 64;
    float acc[4][4] = {};
    for (int k0 = 0; k0 < DD; k0 += 16) {
        float4 a = *reinterpret_cast<const float4*>(Wq + (k0 + ty) * DD + d0 + tx * 4);
        float4 b = *reinterpret_cast<const float4*>(Wk + (k0 + ty) * DD + e0 + tx * 4);
        *reinterpret_cast<float4*>(&As[ty][tx * 4]) = a;
        *reinterpret_cast<float4*>(&Bs[ty][tx * 4]) = b;
        __syncthreads();
        mma_tile4(As, Bs, ty, tx, acc);
        __syncthreads();
    }
#pragma unroll
    for (int i = 0; i < 4; ++i)
#pragma unroll
        for (int j = 0; j < 4; ++j)
            g_W2[(d0 + ty * 4 + i) * DD + e0 + tx * 4 + j] = scale * acc[i][j];
}

// ---------------- kernel A2: bias vectors ----------------------------------
__global__ __launch_bounds__(256) void prep_vec(const float* __restrict__ Wq,
                                                const float* __restrict__ bq,
                                                const float* __restrict__ Wk,
                                                const float* __restrict__ bk) {
    const float scale = 0.0625f;
    int t = threadIdx.x;
    if (blockIdx.x == 0) {
        float s = 0.f;
        for (int k = 0; k < DD; ++k) s = fmaf(Wq[k * DD + t], bk[k], s);
        g_u[t] = scale * s;
        if (t == 0) {
            float c = 0.f;
            for (int k = 0; k < DD; ++k) c = fmaf(bq[k], bk[k], c);
            g_c = scale * c;
        }
    } else {
        float s = 0.f;
        for (int k = 0; k < DD; ++k) s = fmaf(bq[k], Wk[k * DD + t], s);
        g_b2[t] = scale * s;
    }
}

// ---------------- big GEMM: C[4096,256] = A @ B (+bias), 64x64 tile, FFMA2 --
template <int BMODE>
__global__ __launch_bounds__(256) void gemm64(const float* __restrict__ Ap,
                                              const float* __restrict__ Bp,
                                              const float* __restrict__ biasp,
                                              float* __restrict__ Cp) {
    __shared__ float As[2][16][68];
    __shared__ float Bs[2][16][68];
    __shared__ float s_u[DD];

    const float* A = (BMODE == 0) ? Ap : g_wsum;
    const float* B = (BMODE == 0) ? g_W2 : Bp;
    const float* bias = (BMODE == 0) ? g_b2 : biasp;
    float* C = (BMODE == 0) ? g_Qk : Cp;

    const int t = threadIdx.x;
    const int tx = t & 15, ty = t >> 4;
    const int m0 = blockIdx.x * 64, n0 = blockIdx.y * 64;
    const int lmA = t >> 2, kA = (t & 3) * 4;
    const int kB = t >> 4, nB = (t & 15) * 4;
    const int nW = t >> 2, kW = (t & 3) * 4;
    const bool qb_active = (BMODE == 0) && (blockIdx.y == 0);

    if (qb_active) s_u[t] = g_u[t];

    float4 a0, b0;
    a0 = *reinterpret_cast<const float4*>(A + (m0 + lmA) * DD + kA);
    if (BMODE == 0)
        b0 = *reinterpret_cast<const float4*>(B + kB * DD + n0 + nB);
    else
        b0 = *reinterpret_cast<const float4*>(B + (n0 + nW) * DD + kW);
    {
        float av[4] = {a0.x, a0.y, a0.z, a0.w};
#pragma unroll
        for (int c = 0; c < 4; ++c) As[0][kA + c][lmA] = av[c];
        if (BMODE == 0) {
            *reinterpret_cast<float4*>(&Bs[0][kB][nB]) = b0;
        } else {
            float bvv[4] = {b0.x, b0.y, b0.z, b0.w};
#pragma unroll
            for (int c = 0; c < 4; ++c) Bs[0][kW + c][nW] = bvv[c];
        }
    }
    __syncthreads();

    unsigned long long acc[2][4];
#pragma unroll
    for (int i = 0; i < 2; ++i)
#pragma unroll
        for (int j = 0; j < 4; ++j) acc[i][j] = pack2(0.f, 0.f);
    float qb_part = 0.f;

    for (int c = 0; c < 16; ++c) {
        const int buf = c & 1;
        if (c + 1 < 16) {
            const int k0 = (c + 1) * 16;
            a0 = *reinterpret_cast<const float4*>(A + (m0 + lmA) * DD + k0 + kA);
            if (BMODE == 0)
                b0 = *reinterpret_cast<const float4*>(B + (k0 + kB) * DD + n0 + nB);
            else
                b0 = *reinterpret_cast<const float4*>(B + (n0 + nW) * DD + k0 + kW);
        }
#pragma unroll
        for (int kk = 0; kk < 16; ++kk) {
            ulonglong2 ap = *reinterpret_cast<const ulonglong2*>(&As[buf][kk][ty * 4]);
            float4 bf = *reinterpret_cast<const float4*>(&Bs[buf][kk][tx * 4]);
            unsigned long long bd0 = pack2(bf.x, bf.x), bd1 = pack2(bf.y, bf.y);
            unsigned long long bd2 = pack2(bf.z, bf.z), bd3 = pack2(bf.w, bf.w);
            unsigned long long a2[2] = {ap.x, ap.y};
#pragma unroll
            for (int i = 0; i < 2; ++i) {
                fma2(acc[i][0], a2[i], bd0);
                fma2(acc[i][1], a2[i], bd1);
                fma2(acc[i][2], a2[i], bd2);
                fma2(acc[i][3], a2[i], bd3);
            }
        }
        if (qb_active) {
#pragma unroll
            for (int j = 0; j < 4; ++j)
                qb_part = fmaf(As[buf][kA + j][lmA], s_u[c * 16 + kA + j], qb_part);
        }
        if (c + 1 < 16) {
            float av[4] = {a0.x, a0.y, a0.z, a0.w};
#pragma unroll
            for (int c2 = 0; c2 < 4; ++c2) As[buf ^ 1][kA + c2][lmA] = av[c2];
            if (BMODE == 0) {
                *reinterpret_cast<float4*>(&Bs[buf ^ 1][kB][nB]) = b0;
            } else {
                float bvv[4] = {b0.x, b0.y, b0.z, b0.w};
#pragma unroll
                for (int c2 = 0; c2 < 4; ++c2) Bs[buf ^ 1][kW + c2][nW] = bvv[c2];
            }
        }
        __syncthreads();
    }

    if (qb_active) {
        float p = qb_part + __shfl_down_sync(0xffffffffu, qb_part, 2);
        p += __shfl_down_sync(0xffffffffu, p, 1);
        if ((t & 3) == 0) g_qb[m0 + lmA] = p + g_c;
    }

    float4 bb = *reinterpret_cast<const float4*>(bias + n0 + tx * 4);
#pragma unroll
    for (int i = 0; i < 2; ++i) {
        const int m = m0 + ty * 4 + 2 * i;
        float lo[4], hi[4];
#pragma unroll
        for (int j = 0; j < 4; ++j) unpack2(acc[i][j], lo[j], hi[j]);
        float4 o0, o1;
        if (BMODE == 1) {
            float s0 = g_S[m], s1 = g_S[m + 1];
            o0 = make_float4(lo[0] + bb.x * s0, lo[1] + bb.y * s0,
                             lo[2] + bb.z * s0, lo[3] + bb.w * s0);
            o1 = make_float4(hi[0] + bb.x * s1, hi[1] + bb.y * s1,
                             hi[2] + bb.z * s1, hi[3] + bb.w * s1);
        } else {
            o0 = make_float4(lo[0] + bb.x, lo[1] + bb.y, lo[2] + bb.z, lo[3] + bb.w);
            o1 = make_float4(hi[0] + bb.x, hi[1] + bb.y, hi[2] + bb.z, hi[3] + bb.w);
        }
        *reinterpret_cast<float4*>(C + (size_t)m * DD + n0 + tx * 4) = o0;
        *reinterpret_cast<float4*>(C + (size_t)(m + 1) * DD + n0 + tx * 4) = o1;
    }
}

// ---------------- attn v6: reg-held anchors, redundant softmax, early refill
__global__ __launch_bounds__(512) void attn_v6(const float* __restrict__ anchor,
                                               const float* __restrict__ sims) {
    extern __shared__ float sm[];
    float* sQk    = sm + NBUF * AA * DD;    // [2][256]
    float* s_sims = sQk + 2 * DD;           // [2][64]
    float* sP     = s_sims + 2 * AA;        // [16][256] warp partials
    __shared__ float s_adj[AA];
    __shared__ __align__(8) unsigned long long mbar[NBUF];

    const int t = threadIdx.x, w = t >> 5, lane = t & 31;
    const int cta = blockIdx.x;
    const int iters = (NROWS - cta + NCTA - 1) / NCTA;

    uint32_t mb_base, sA_base;
    asm("{ .reg .u64 x; cvta.to.shared.u64 x, %1; cvt.u32.u64 %0, x; }"
        : "=r"(mb_base) : "l"(mbar));
    asm("{ .reg .u64 x; cvta.to.shared.u64 x, %1; cvt.u32.u64 %0, x; }"
        : "=r"(sA_base) : "l"(sm));

    if (t == 0) {
#pragma unroll
        for (int j = 0; j < NBUF; ++j)
            asm volatile("mbarrier.init.shared::cta.b64 [%0], 1;"
                         :: "r"(mb_base + j * 8));
    }
    __syncthreads();
    if (t == 0) {
#pragma unroll
        for (int j = 0; j < NBUF; ++j)
            if (j < iters) {
                uint32_t mb = mb_base + j * 8;
                asm volatile("mbarrier.arrive.expect_tx.shared::cta.b64 _, [%0], %1;"
                             :: "r"(mb), "r"(65536));
                asm volatile(
                    "cp.async.bulk.shared::cta.global.mbarrier::complete_tx::bytes "
                    "[%0], [%1], %2, [%3];"
                    :: "r"(sA_base + j * 65536),
                       "l"(anchor + (size_t)(cta + j * NCTA) * AA * DD),
                       "r"(65536), "r"(mb) : "memory");
            }
    }
    // preload row0 vectors
    if (t < DD) sQk[t] = g_Qk[cta * DD + t];
    if (t < AA) s_sims[t] = sims[cta * AA + t];
    float qb_cur = g_qb[cta];
    int phase[NBUF];
#pragma unroll
    for (int j = 0; j < NBUF; ++j) phase[j] = 0;
    __syncthreads();

    for (int it = 0; it < iters; ++it) {
        const int row = cta + it * NCTA;
        const int b = it % NBUF;
        const int cb = it & 1;
        const float* sA = sm + b * AA * DD;

        // prefetch next row vectors into regs (upper half parks them later)
        const bool has_next = (it + 1 < iters);
        float r_qk = 0.f, r_sims = 0.f, r_qb = 0.f;
        if (has_next) {
            const int nrow = row + NCTA;
            if (t >= 256) {
                const int tt = t - 256;
                r_qk = g_Qk[nrow * DD + tt];
                if (tt < AA) r_sims = sims[nrow * AA + tt];
            }
            r_qb = g_qb[nrow];
        }

        // hoist Qk for this row (lane-contiguous float4, conflict-free)
        const float4* q4 = reinterpret_cast<const float4*>(sQk + cb * DD);
        float4 q0 = q4[lane], q1 = q4[lane + 32];

        // wait for this buffer's tile
        {
            uint32_t mb = mb_base + b * 8;
            asm volatile(
                "{ .reg .pred P;\n"
                "WL%=: mbarrier.try_wait.parity.acquire.cta.shared::cta.b64 P, [%0], %1;\n"
                "@!P bra WL%=; }"
                :: "r"(mb), "r"(phase[b]) : "memory");
            phase[b] ^= 1;
        }

        // scores: warp per anchor, 4 rounds (a = w + 16*r); KEEP anchors in regs
        float4 x0[4], x1[4];
#pragma unroll
        for (int r = 0; r < 4; ++r) {
            const int a = w + r * 16;
            const float4* a4 = reinterpret_cast<const float4*>(sA + a * DD);
            x0[r] = a4[lane];
            x1[r] = a4[lane + 32];
            float s = q0.x * x0[r].x + q0.y * x0[r].y + q0.z * x0[r].z +
                      q0.w * x0[r].w + q1.x * x1[r].x + q1.y * x1[r].y +
                      q1.z * x1[r].z + q1.w * x1[r].w;
#pragma unroll
            for (int o = 16; o; o >>= 1) s += __shfl_down_sync(0xffffffffu, s, o);
            if (lane == 0) s_adj[a] = s + qb_cur + s_sims[cb * AA + a];
        }
        __syncthreads();  // bar1: s_adj complete; all sA reads done

        // refill this buffer NOW (tile only read in score pass)
        if (t == 0 && it + NBUF < iters) {
            uint32_t mb = mb_base + b * 8;
            asm volatile("mbarrier.arrive.expect_tx.shared::cta.b64 _, [%0], %1;"
                         :: "r"(mb), "r"(65536));
            asm volatile(
                "cp.async.bulk.shared::cta.global.mbarrier::complete_tx::bytes "
                "[%0], [%1], %2, [%3];"
                :: "r"(sA_base + b * 65536),
                   "l"(anchor + (size_t)(row + NBUF * NCTA) * AA * DD),
                   "r"(65536), "r"(mb) : "memory");
        }

        // redundant softmax in every warp (no single-warp bottleneck)
        float p0, p1;
        {
            float v0 = s_adj[lane], v1 = s_adj[lane + 32];
            float sum = v0 + v1;
            float mx = fmaxf(v0, v1);
#pragma unroll
            for (int o = 16; o; o >>= 1) {
                sum += __shfl_xor_sync(0xffffffffu, sum, o);
                mx = fmaxf(mx, __shfl_xor_sync(0xffffffffu, mx, o));
            }
            if (sum != 0.0f) {
                float e0 = __expf(v0 - mx), e1 = __expf(v1 - mx);
                float es = e0 + e1;
#pragma unroll
                for (int o = 16; o; o >>= 1) es += __shfl_xor_sync(0xffffffffu, es, o);
                float inv = 1.0f / es;
                p0 = e0 * inv;
                p1 = e1 * inv;
                if (t == 0) g_S[row] = 1.0f;
            } else {
                p0 = v0;
                p1 = v1;
                if (t == 0) g_S[row] = 0.0f;
            }
        }
        // this warp's 4 probabilities: a = w, w+16, w+32, w+48
        float pa0 = __shfl_sync(0xffffffffu, p0, w);
        float pa1 = __shfl_sync(0xffffffffu, p0, w + 16);
        float pa2 = __shfl_sync(0xffffffffu, p1, w);
        float pa3 = __shfl_sync(0xffffffffu, p1, w + 16);

        // per-warp weighted partial from reg-held anchors
        float4 acc0, acc1;
        acc0.x = pa0 * x0[0].x; acc0.y = pa0 * x0[0].y;
        acc0.z = pa0 * x0[0].z; acc0.w = pa0 * x0[0].w;
        acc1.x = pa0 * x1[0].x; acc1.y = pa0 * x1[0].y;
        acc1.z = pa0 * x1[0].z; acc1.w = pa0 * x1[0].w;
        acc0.x = fmaf(pa1, x0[1].x, acc0.x); acc0.y = fmaf(pa1, x0[1].y, acc0.y);
        acc0.z = fmaf(pa1, x0[1].z, acc0.z); acc0.w = fmaf(pa1, x0[1].w, acc0.w);
        acc1.x = fmaf(pa1, x1[1].x, acc1.x); acc1.y = fmaf(pa1, x1[1].y, acc1.y);
        acc1.z = fmaf(pa1, x1[1].z, acc1.z); acc1.w = fmaf(pa1, x1[1].w, acc1.w);
        acc0.x = fmaf(pa2, x0[2].x, acc0.x); acc0.y = fmaf(pa2, x0[2].y, acc0.y);
        acc0.z = fmaf(pa2, x0[2].z, acc0.z); acc0.w = fmaf(pa2, x0[2].w, acc0.w);
        acc1.x = fmaf(pa2, x1[2].x, acc1.x); acc1.y = fmaf(pa2, x1[2].y, acc1.y);
        acc1.z = fmaf(pa2, x1[2].z, acc1.z); acc1.w = fmaf(pa2, x1[2].w, acc1.w);
        acc0.x = fmaf(pa3, x0[3].x, acc0.x); acc0.y = fmaf(pa3, x0[3].y, acc0.y);
        acc0.z = fmaf(pa3, x0[3].z, acc0.z); acc0.w = fmaf(pa3, x0[3].w, acc0.w);
        acc1.x = fmaf(pa3, x1[3].x, acc1.x); acc1.y = fmaf(pa3, x1[3].y, acc1.y);
        acc1.z = fmaf(pa3, x1[3].z, acc1.z); acc1.w = fmaf(pa3, x1[3].w, acc1.w);
        *reinterpret_cast<float4*>(&sP[w * DD + lane * 4]) = acc0;
        *reinterpret_cast<float4*>(&sP[w * DD + 128 + lane * 4]) = acc1;
        __syncthreads();  // bar2: partials ready

        // lower half reduces 16 partials; upper half parks next-row vectors
        if (t < 256) {
            float a = 0.f;
#pragma unroll
            for (int i = 0; i < 16; ++i) a += sP[i * DD + t];
            g_wsum[row * DD + t] = a;
        } else if (has_next) {
            const int tt = t - 256;
            sQk[(cb ^ 1) * DD + tt] = r_qk;
            if (tt < AA) s_sims[(cb ^ 1) * AA + tt] = r_sims;
        }
        qb_cur = r_qb;
        __syncthreads();  // bar3: parking visible; sP reusable
    }
}

// ---------------- launch ----------------------------------------------------
extern "C" void kernel_launch(void* const* d_in, const int* in_sizes, int n_in,
                              void* d_out, int out_size) {
    const float* cc     = (const float*)d_in[0];
    const float* anchor = (const float*)d_in[1];
    const float* sims   = (const float*)d_in[2];
    const float* Wq     = (const float*)d_in[3];
    const float* bq     = (const float*)d_in[4];
    const float* Wk     = (const float*)d_in[5];
    const float* bk     = (const float*)d_in[6];
    const float* Wv     = (const float*)d_in[7];
    const float* bv     = (const float*)d_in[8];
    float* out = (float*)d_out;

    const int smem_attn =
        (NBUF * AA * DD + 2 * DD + 2 * AA + 16 * DD) * (int)sizeof(float);  // ~210.5 KB
    cudaFuncSetAttribute(attn_v6, cudaFuncAttributeMaxDynamicSharedMemorySize,
                         smem_attn);

    prep_w2<<<dim3(4, 4), 256>>>(Wq, Wk);
    prep_vec<<<2, 256>>>(Wq, bq, Wk, bk);
    gemm64<0><<<dim3(64, 4), 256>>>(cc, nullptr, nullptr, nullptr);
    attn_v6<<<NCTA, 512, smem_attn>>>(anchor, sims);
    gemm64<1><<<dim3(64, 4), 256>>>(nullptr, Wv, bv, out);
}

// round 9
// speedup vs baseline: 2.1355x; 1.2300x over previous
#include <cuda_runtime.h>
#include <math.h>
#include <stdint.h>

#define DD 256
#define AA 64
#define NROWS 4096   // B*N
#define NCTA 148     // persistent CTAs for attn
#define NBUF 3       // pipeline depth

// ---------------- scratch (device globals; no allocation allowed) ----------
__device__ float g_W2[DD * DD];      // scale * Wq^T @ Wk
__device__ float g_b2[DD];           // scale * bq @ Wk
__device__ float g_u[DD];            // scale * Wq^T @ bk
__device__ float g_c;                // scale * bq . bk
__device__ float g_Qk[NROWS * DD];   // cc @ g_W2 + g_b2
__device__ float g_qb[NROWS];        // cc_row . g_u + g_c
__device__ float g_wsum[NROWS * DD]; // sum_a p[a] * anchor[a,:]
__device__ float g_S[NROWS];         // sum_a p[a]

// ---------------- f32x2 helpers ---------------------------------------------
__device__ __forceinline__ unsigned long long pack2(float x, float y) {
    unsigned long long r;
    asm("mov.b64 %0, {%1, %2};" : "=l"(r) : "f"(x), "f"(y));
    return r;
}
__device__ __forceinline__ void unpack2(unsigned long long v, float& x, float& y) {
    asm("mov.b64 {%0, %1}, %2;" : "=f"(x), "=f"(y) : "l"(v));
}
__device__ __forceinline__ void fma2(unsigned long long& d, unsigned long long a,
                                     unsigned long long b) {
    asm("fma.rn.f32x2 %0, %1, %2, %0;" : "+l"(d) : "l"(a), "l"(b));
}

// ---------------- merged prep: blocks 0-15 -> W2 tiles; 16,17 -> vectors ----
__device__ __forceinline__ void mma_tile4(const float (*As)[68], const float (*Bs)[68],
                                          int ty, int tx, float acc[4][4]) {
#pragma unroll
    for (int kk = 0; kk < 16; ++kk) {
        float4 av = *reinterpret_cast<const float4*>(&As[kk][ty * 4]);
        float4 bv = *reinterpret_cast<const float4*>(&Bs[kk][tx * 4]);
        float ar[4] = {av.x, av.y, av.z, av.w};
        float br[4] = {bv.x, bv.y, bv.z, bv.w};
#pragma unroll
        for (int i = 0; i < 4; ++i)
#pragma unroll
            for (int j = 0; j < 4; ++j)
                acc[i][j] = fmaf(ar[i], br[j], acc[i][j]);
    }
}

__global__ __launch_bounds__(256) void prep_all(const float* __restrict__ Wq,
                                                const float* __restrict__ bq,
                                                const float* __restrict__ Wk,
                                                const float* __restrict__ bk) {
    const float scale = 0.0625f;  // 1/sqrt(256)
    const int blk = blockIdx.x;
    const int t = threadIdx.x;
    if (blk >= 16) {
        if (blk == 16) {
            float s = 0.f;
            for (int k = 0; k < DD; ++k) s = fmaf(Wq[k * DD + t], bk[k], s);
            g_u[t] = scale * s;
            if (t == 0) {
                float c = 0.f;
                for (int k = 0; k < DD; ++k) c = fmaf(bq[k], bk[k], c);
                g_c = scale * c;
            }
        } else {
            float s = 0.f;
            for (int k = 0; k < DD; ++k) s = fmaf(bq[k], Wk[k * DD + t], s);
            g_b2[t] = scale * s;
        }
        return;
    }
    __shared__ float As[16][68];
    __shared__ float Bs[16][68];
    int tx = t % 16, ty = t / 16;
    int d0 = (blk % 4) * 64, e0 = (blk / 4) * 64;
    float acc[4][4] = {};
    for (int k0 = 0; k0 < DD; k0 += 16) {
        float4 a = *reinterpret_cast<const float4*>(Wq + (k0 + ty) * DD + d0 + tx * 4);
        float4 b = *reinterpret_cast<const float4*>(Wk + (k0 + ty) * DD + e0 + tx * 4);
        *reinterpret_cast<float4*>(&As[ty][tx * 4]) = a;
        *reinterpret_cast<float4*>(&Bs[ty][tx * 4]) = b;
        __syncthreads();
        mma_tile4(As, Bs, ty, tx, acc);
        __syncthreads();
    }
#pragma unroll
    for (int i = 0; i < 4; ++i)
#pragma unroll
        for (int j = 0; j < 4; ++j)
            g_W2[(d0 + ty * 4 + i) * DD + e0 + tx * 4 + j] = scale * acc[i][j];
}

// ---------------- big GEMM: C[4096,256] = A @ B (+bias), 64x64 tile, FFMA2 --
template <int BMODE>
__global__ __launch_bounds__(256) void gemm64(const float* __restrict__ Ap,
                                              const float* __restrict__ Bp,
                                              const float* __restrict__ biasp,
                                              float* __restrict__ Cp) {
    __shared__ float As[2][16][68];
    __shared__ float Bs[2][16][68];
    __shared__ float s_u[DD];

    const float* A = (BMODE == 0) ? Ap : g_wsum;
    const float* B = (BMODE == 0) ? g_W2 : Bp;
    const float* bias = (BMODE == 0) ? g_b2 : biasp;
    float* C = (BMODE == 0) ? g_Qk : Cp;

    const int t = threadIdx.x;
    const int tx = t & 15, ty = t >> 4;
    const int m0 = blockIdx.x * 64, n0 = blockIdx.y * 64;
    const int lmA = t >> 2, kA = (t & 3) * 4;
    const int kB = t >> 4, nB = (t & 15) * 4;
    const int nW = t >> 2, kW = (t & 3) * 4;
    const bool qb_active = (BMODE == 0) && (blockIdx.y == 0);

    if (qb_active) s_u[t] = g_u[t];

    float4 a0, b0;
    a0 = *reinterpret_cast<const float4*>(A + (m0 + lmA) * DD + kA);
    if (BMODE == 0)
        b0 = *reinterpret_cast<const float4*>(B + kB * DD + n0 + nB);
    else
        b0 = *reinterpret_cast<const float4*>(B + (n0 + nW) * DD + kW);
    {
        float av[4] = {a0.x, a0.y, a0.z, a0.w};
#pragma unroll
        for (int c = 0; c < 4; ++c) As[0][kA + c][lmA] = av[c];
        if (BMODE == 0) {
            *reinterpret_cast<float4*>(&Bs[0][kB][nB]) = b0;
        } else {
            float bvv[4] = {b0.x, b0.y, b0.z, b0.w};
#pragma unroll
            for (int c = 0; c < 4; ++c) Bs[0][kW + c][nW] = bvv[c];
        }
    }
    __syncthreads();

    unsigned long long acc[2][4];
#pragma unroll
    for (int i = 0; i < 2; ++i)
#pragma unroll
        for (int j = 0; j < 4; ++j) acc[i][j] = pack2(0.f, 0.f);
    float qb_part = 0.f;

    for (int c = 0; c < 16; ++c) {
        const int buf = c & 1;
        if (c + 1 < 16) {
            const int k0 = (c + 1) * 16;
            a0 = *reinterpret_cast<const float4*>(A + (m0 + lmA) * DD + k0 + kA);
            if (BMODE == 0)
                b0 = *reinterpret_cast<const float4*>(B + (k0 + kB) * DD + n0 + nB);
            else
                b0 = *reinterpret_cast<const float4*>(B + (n0 + nW) * DD + k0 + kW);
        }
#pragma unroll
        for (int kk = 0; kk < 16; ++kk) {
            ulonglong2 ap = *reinterpret_cast<const ulonglong2*>(&As[buf][kk][ty * 4]);
            float4 bf = *reinterpret_cast<const float4*>(&Bs[buf][kk][tx * 4]);
            unsigned long long bd0 = pack2(bf.x, bf.x), bd1 = pack2(bf.y, bf.y);
            unsigned long long bd2 = pack2(bf.z, bf.z), bd3 = pack2(bf.w, bf.w);
            unsigned long long a2[2] = {ap.x, ap.y};
#pragma unroll
            for (int i = 0; i < 2; ++i) {
                fma2(acc[i][0], a2[i], bd0);
                fma2(acc[i][1], a2[i], bd1);
                fma2(acc[i][2], a2[i], bd2);
                fma2(acc[i][3], a2[i], bd3);
            }
        }
        if (qb_active) {
#pragma unroll
            for (int j = 0; j < 4; ++j)
                qb_part = fmaf(As[buf][kA + j][lmA], s_u[c * 16 + kA + j], qb_part);
        }
        if (c + 1 < 16) {
            float av[4] = {a0.x, a0.y, a0.z, a0.w};
#pragma unroll
            for (int c2 = 0; c2 < 4; ++c2) As[buf ^ 1][kA + c2][lmA] = av[c2];
            if (BMODE == 0) {
                *reinterpret_cast<float4*>(&Bs[buf ^ 1][kB][nB]) = b0;
            } else {
                float bvv[4] = {b0.x, b0.y, b0.z, b0.w};
#pragma unroll
                for (int c2 = 0; c2 < 4; ++c2) Bs[buf ^ 1][kW + c2][nW] = bvv[c2];
            }
        }
        __syncthreads();
    }

    if (qb_active) {
        float p = qb_part + __shfl_down_sync(0xffffffffu, qb_part, 2);
        p += __shfl_down_sync(0xffffffffu, p, 1);
        if ((t & 3) == 0) g_qb[m0 + lmA] = p + g_c;
    }

    float4 bb = *reinterpret_cast<const float4*>(bias + n0 + tx * 4);
#pragma unroll
    for (int i = 0; i < 2; ++i) {
        const int m = m0 + ty * 4 + 2 * i;
        float lo[4], hi[4];
#pragma unroll
        for (int j = 0; j < 4; ++j) unpack2(acc[i][j], lo[j], hi[j]);
        float4 o0, o1;
        if (BMODE == 1) {
            float s0 = g_S[m], s1 = g_S[m + 1];
            o0 = make_float4(lo[0] + bb.x * s0, lo[1] + bb.y * s0,
                             lo[2] + bb.z * s0, lo[3] + bb.w * s0);
            o1 = make_float4(hi[0] + bb.x * s1, hi[1] + bb.y * s1,
                             hi[2] + bb.z * s1, hi[3] + bb.w * s1);
        } else {
            o0 = make_float4(lo[0] + bb.x, lo[1] + bb.y, lo[2] + bb.z, lo[3] + bb.w);
            o1 = make_float4(hi[0] + bb.x, hi[1] + bb.y, hi[2] + bb.z, hi[3] + bb.w);
        }
        *reinterpret_cast<float4*>(C + (size_t)m * DD + n0 + tx * 4) = o0;
        *reinterpret_cast<float4*>(C + (size_t)(m + 1) * DD + n0 + tx * 4) = o1;
    }
}

// ---------------- attn v7: two independent 256-thread halves per CTA --------
// Half h processes rows it = h, h+2, ... Buffers rotate globally (it % 3),
// parity = (it/3)&1. Tile is dead after the score pass (anchors held in regs),
// so the consuming half refills its buffer right after its score barrier.
__global__ __launch_bounds__(512) void attn_v7(const float* __restrict__ anchor,
                                               const float* __restrict__ sims) {
    extern __shared__ float sm[];
    float* sP = sm + NBUF * AA * DD;  // [2 halves][8 warps][256]
    __shared__ float s_adj[2][AA];
    __shared__ __align__(8) unsigned long long mbar[NBUF];

    const int t = threadIdx.x;
    const int half = t >> 8;      // 0 or 1
    const int th = t & 255;       // thread within half
    const int w = th >> 5;        // warp within half (0..7)
    const int lane = t & 31;
    const int cta = blockIdx.x;
    const int iters = (NROWS - cta + NCTA - 1) / NCTA;

    uint32_t mb_base, sA_base;
    asm("{ .reg .u64 x; cvta.to.shared.u64 x, %1; cvt.u32.u64 %0, x; }"
        : "=r"(mb_base) : "l"(mbar));
    asm("{ .reg .u64 x; cvta.to.shared.u64 x, %1; cvt.u32.u64 %0, x; }"
        : "=r"(sA_base) : "l"(sm));

    if (t == 0) {
#pragma unroll
        for (int j = 0; j < NBUF; ++j)
            asm volatile("mbarrier.init.shared::cta.b64 [%0], 1;"
                         :: "r"(mb_base + j * 8));
    }
    __syncthreads();
    if (t == 0) {
#pragma unroll
        for (int j = 0; j < NBUF; ++j)
            if (j < iters) {
                uint32_t mb = mb_base + j * 8;
                asm volatile("mbarrier.arrive.expect_tx.shared::cta.b64 _, [%0], %1;"
                             :: "r"(mb), "r"(65536));
                asm volatile(
                    "cp.async.bulk.shared::cta.global.mbarrier::complete_tx::bytes "
                    "[%0], [%1], %2, [%3];"
                    :: "r"(sA_base + j * 65536),
                       "l"(anchor + (size_t)(cta + j * NCTA) * AA * DD),
                       "r"(65536), "r"(mb) : "memory");
            }
    }
    __syncthreads();

    const int bar_id = 1 + half;

    for (int it = half; it < iters; it += 2) {
        const int row = cta + it * NCTA;
        const int b = it % NBUF;
        const float* sA = sm + b * AA * DD;

        // row vectors via LDG (L2-resident; latency hides under mbarrier wait)
        const float4* qg = reinterpret_cast<const float4*>(g_Qk + (size_t)row * DD);
        float4 q0 = qg[lane], q1 = qg[lane + 32];
        float qb = g_qb[row];
        float simv = (lane < 8) ? sims[row * AA + w + 8 * lane] : 0.f;

        // wait for this tile (fill index = it/3, parity = (it/3)&1)
        {
            uint32_t mb = mb_base + b * 8;
            int par = (it / NBUF) & 1;
            asm volatile(
                "{ .reg .pred P;\n"
                "WL%=: mbarrier.try_wait.parity.acquire.cta.shared::cta.b64 P, [%0], %1;\n"
                "@!P bra WL%=; }"
                :: "r"(mb), "r"(par) : "memory");
        }

        // scores: this warp owns anchors a = w + 8j (j=0..7); keep anchors in regs
        float4 x0[8], x1[8];
        float val = 0.f;
#pragma unroll
        for (int j = 0; j < 8; ++j) {
            const int a = w + 8 * j;
            const float4* a4 = reinterpret_cast<const float4*>(sA + a * DD);
            x0[j] = a4[lane];
            x1[j] = a4[lane + 32];
            float s = q0.x * x0[j].x + q0.y * x0[j].y + q0.z * x0[j].z +
                      q0.w * x0[j].w + q1.x * x1[j].x + q1.y * x1[j].y +
                      q1.z * x1[j].z + q1.w * x1[j].w;
#pragma unroll
            for (int o = 16; o; o >>= 1) s += __shfl_xor_sync(0xffffffffu, s, o);
            if (lane == j) val = s + qb + simv;  // lane j owns anchor w+8j
        }
        if (lane < 8) s_adj[half][w + 8 * lane] = val;

        asm volatile("bar.sync %0, 256;" :: "r"(bar_id) : "memory");  // scores done

        // refill this buffer for global iteration it+3 (other half consumes)
        if (th == 0 && it + NBUF < iters) {
            uint32_t mb = mb_base + b * 8;
            asm volatile("mbarrier.arrive.expect_tx.shared::cta.b64 _, [%0], %1;"
                         :: "r"(mb), "r"(65536));
            asm volatile(
                "cp.async.bulk.shared::cta.global.mbarrier::complete_tx::bytes "
                "[%0], [%1], %2, [%3];"
                :: "r"(sA_base + b * 65536),
                   "l"(anchor + (size_t)(row + NBUF * NCTA) * AA * DD),
                   "r"(65536), "r"(mb) : "memory");
        }

        // redundant softmax in every warp of this half
        float p0, p1;
        {
            float v0 = s_adj[half][lane], v1 = s_adj[half][lane + 32];
            float sum = v0 + v1;
            float mx = fmaxf(v0, v1);
#pragma unroll
            for (int o = 16; o; o >>= 1) {
                sum += __shfl_xor_sync(0xffffffffu, sum, o);
                mx = fmaxf(mx, __shfl_xor_sync(0xffffffffu, mx, o));
            }
            if (sum != 0.0f) {
                float e0 = __expf(v0 - mx), e1 = __expf(v1 - mx);
                float es = e0 + e1;
#pragma unroll
                for (int o = 16; o; o >>= 1) es += __shfl_xor_sync(0xffffffffu, es, o);
                float inv = 1.0f / es;
                p0 = e0 * inv;
                p1 = e1 * inv;
                if (th == 0) g_S[row] = 1.0f;
            } else {
                p0 = v0;
                p1 = v1;
                if (th == 0) g_S[row] = 0.0f;
            }
        }
        // gather this warp's 8 probabilities (anchors w+8j)
        float pa[8];
#pragma unroll
        for (int j = 0; j < 4; ++j)
            pa[j] = __shfl_sync(0xffffffffu, p0, w + 8 * j);
#pragma unroll
        for (int j = 4; j < 8; ++j)
            pa[j] = __shfl_sync(0xffffffffu, p1, w + 8 * j - 32);

        // weighted partial from reg-held anchors
        float4 acc0 = make_float4(0.f, 0.f, 0.f, 0.f);
        float4 acc1 = make_float4(0.f, 0.f, 0.f, 0.f);
#pragma unroll
        for (int j = 0; j < 8; ++j) {
            acc0.x = fmaf(pa[j], x0[j].x, acc0.x);
            acc0.y = fmaf(pa[j], x0[j].y, acc0.y);
            acc0.z = fmaf(pa[j], x0[j].z, acc0.z);
            acc0.w = fmaf(pa[j], x0[j].w, acc0.w);
            acc1.x = fmaf(pa[j], x1[j].x, acc1.x);
            acc1.y = fmaf(pa[j], x1[j].y, acc1.y);
            acc1.z = fmaf(pa[j], x1[j].z, acc1.z);
            acc1.w = fmaf(pa[j], x1[j].w, acc1.w);
        }
        float* myP = sP + (half * 8 + w) * DD;
        *reinterpret_cast<float4*>(myP + lane * 4) = acc0;
        *reinterpret_cast<float4*>(myP + 128 + lane * 4) = acc1;

        asm volatile("bar.sync %0, 256;" :: "r"(bar_id) : "memory");  // partials ready

        // reduce 8 partials -> g_wsum (also orders sP reuse vs next iter's writes
        // via the score barrier of the next iteration)
        {
            const float* hp = sP + half * 8 * DD;
            float a = 0.f;
#pragma unroll
            for (int i = 0; i < 8; ++i) a += hp[i * DD + th];
            g_wsum[(size_t)row * DD + th] = a;
        }
    }
}

// ---------------- launch ----------------------------------------------------
extern "C" void kernel_launch(void* const* d_in, const int* in_sizes, int n_in,
                              void* d_out, int out_size) {
    const float* cc     = (const float*)d_in[0];
    const float* anchor = (const float*)d_in[1];
    const float* sims   = (const float*)d_in[2];
    const float* Wq     = (const float*)d_in[3];
    const float* bq     = (const float*)d_in[4];
    const float* Wk     = (const float*)d_in[5];
    const float* bk     = (const float*)d_in[6];
    const float* Wv     = (const float*)d_in[7];
    const float* bv     = (const float*)d_in[8];
    float* out = (float*)d_out;

    const int smem_attn = (NBUF * AA * DD + 16 * DD) * (int)sizeof(float);  // 208 KB
    cudaFuncSetAttribute(attn_v7, cudaFuncAttributeMaxDynamicSharedMemorySize,
                         smem_attn);

    prep_all<<<18, 256>>>(Wq, bq, Wk, bk);
    gemm64<0><<<dim3(64, 4), 256>>>(cc, nullptr, nullptr, nullptr);
    attn_v7<<<NCTA, 512, smem_attn>>>(anchor, sims);
    gemm64<1><<<dim3(64, 4), 256>>>(nullptr, Wv, bv, out);
}